// round 2
// baseline (speedup 1.0000x reference)
#include <cuda_runtime.h>

#define T_STEPS 16
#define BATCH   32768
#define HID     256
#define RB      32            // batch rows per block
#define NBLK    (BATCH / RB)  // 1024 blocks

// Transposed weights (column-contiguous for sum-of-columns GEMM)
__device__ float g_w2t[HID * HID];   // [i][o]
__device__ float g_w3t[HID * HID];   // [i][o]
__device__ float g_w4t[HID * 16];    // [i][o4]

__global__ void prep_kernel(const float* __restrict__ w2,
                            const float* __restrict__ w3,
                            const float* __restrict__ w4) {
    int idx = blockIdx.x * 256 + threadIdx.x;   // 0..65535
    int o = idx >> 8;
    int i = idx & 255;
    g_w2t[i * HID + o] = w2[idx];               // w2 is [o][i] row-major
    g_w3t[i * HID + o] = w3[idx];
    if (idx < 16 * HID) {
        int oo = idx >> 8;                      // 0..15
        int ii = idx & 255;
        g_w4t[ii * 16 + oo] = w4[idx];          // w4 is [16][256]
    }
}

// ---- packed f32x2 helpers (Blackwell sm_103a) ----
__device__ __forceinline__ unsigned long long pk2(float a, float b) {
    unsigned long long r;
    asm("mov.b64 %0, {%1,%2};" : "=l"(r) : "f"(a), "f"(b));
    return r;
}
__device__ __forceinline__ void up2(unsigned long long v, float& a, float& b) {
    asm("mov.b64 {%0,%1}, %2;" : "=f"(a), "=f"(b) : "l"(v));
}
__device__ __forceinline__ void ffma2(unsigned long long& d,
                                      unsigned long long a,
                                      unsigned long long b) {
    asm("fma.rn.f32x2 %0, %1, %2, %0;" : "+l"(d) : "l"(a), "l"(b));
}

__global__ __launch_bounds__(256, 1)
void snn_kernel(const float* __restrict__ x,
                const float* __restrict__ w1,
                float* __restrict__ out) {
    // spike buffer: [neuron i][quad q] -> spikes (0/1) of rows 4q..4q+3
    // padded to 9 float4 per row to avoid STS bank conflicts
    __shared__ float4 s_spk[HID][9];
    __shared__ float  s_x[RB][16];

    const int tid = threadIdx.x;
    const int rb  = blockIdx.x * RB;
    const int o   = tid;

    // load x tile
    for (int idx = tid; idx < RB * 16; idx += 256) {
        int r = idx >> 4, k = idx & 15;
        s_x[r][k] = x[(rb + r) * 16 + k];
    }
    // this thread's w1 row (output neuron o)
    float wr[16];
#pragma unroll
    for (int k = 0; k < 16; k++) wr[k] = __ldg(&w1[o * 16 + k]);
    __syncthreads();

    float v1[RB], v2[RB], v3[RB];
#pragma unroll
    for (int r = 0; r < RB; r++) { v1[r] = 0.f; v2[r] = 0.f; v3[r] = 0.f; }

    const int  o4     = tid & 15;
    const int  g      = tid >> 4;       // 16 row-pair groups
    const int  q4     = g >> 1;
    const bool hiPair = (g & 1);

    for (int t = 0; t < T_STEPS; t++) {
        // ================= layer 1 IF (a1 recomputed; constant over t) ======
#pragma unroll
        for (int qq = 0; qq < 8; qq++) {
            float sp[4];
#pragma unroll
            for (int j = 0; j < 4; j++) {
                int r = qq * 4 + j;
                float a = 0.f;
#pragma unroll
                for (int k = 0; k < 16; k++) a = fmaf(wr[k], s_x[r][k], a);
                float v = v1[r] + a;
                float s = (v >= 1.0f) ? 1.0f : 0.0f;
                v1[r] = v - s;
                sp[j] = s;
            }
            s_spk[o][qq] = make_float4(sp[0], sp[1], sp[2], sp[3]);
        }
        __syncthreads();

        // ================= layer 2: GEMM (sum of spiking columns) + IF ======
        {
            unsigned long long h[16];
#pragma unroll
            for (int p = 0; p < 16; p++) h[p] = 0ull;
#pragma unroll 4
            for (int i = 0; i < HID; i++) {
                float c = __ldg(&g_w2t[i * HID + o]);
                unsigned long long c2 = pk2(c, c);
#pragma unroll
                for (int qq = 0; qq < 8; qq++) {
                    float4 f = s_spk[i][qq];
                    ffma2(h[2 * qq],     pk2(f.x, f.y), c2);
                    ffma2(h[2 * qq + 1], pk2(f.z, f.w), c2);
                }
            }
            __syncthreads();   // everyone done reading s1 before overwrite
#pragma unroll
            for (int qq = 0; qq < 8; qq++) {
                float h0, h1, h2, h3;
                up2(h[2 * qq],     h0, h1);
                up2(h[2 * qq + 1], h2, h3);
                float v, s0, s1, s2, s3;
                v = v2[4*qq+0] + h0; s0 = (v >= 1.f) ? 1.f : 0.f; v2[4*qq+0] = v - s0;
                v = v2[4*qq+1] + h1; s1 = (v >= 1.f) ? 1.f : 0.f; v2[4*qq+1] = v - s1;
                v = v2[4*qq+2] + h2; s2 = (v >= 1.f) ? 1.f : 0.f; v2[4*qq+2] = v - s2;
                v = v2[4*qq+3] + h3; s3 = (v >= 1.f) ? 1.f : 0.f; v2[4*qq+3] = v - s3;
                s_spk[o][qq] = make_float4(s0, s1, s2, s3);
            }
        }
        __syncthreads();

        // ================= layer 3: GEMM + IF ===============================
        {
            unsigned long long h[16];
#pragma unroll
            for (int p = 0; p < 16; p++) h[p] = 0ull;
#pragma unroll 4
            for (int i = 0; i < HID; i++) {
                float c = __ldg(&g_w3t[i * HID + o]);
                unsigned long long c2 = pk2(c, c);
#pragma unroll
                for (int qq = 0; qq < 8; qq++) {
                    float4 f = s_spk[i][qq];
                    ffma2(h[2 * qq],     pk2(f.x, f.y), c2);
                    ffma2(h[2 * qq + 1], pk2(f.z, f.w), c2);
                }
            }
            __syncthreads();
#pragma unroll
            for (int qq = 0; qq < 8; qq++) {
                float h0, h1, h2, h3;
                up2(h[2 * qq],     h0, h1);
                up2(h[2 * qq + 1], h2, h3);
                float v, s0, s1, s2, s3;
                v = v3[4*qq+0] + h0; s0 = (v >= 1.f) ? 1.f : 0.f; v3[4*qq+0] = v - s0;
                v = v3[4*qq+1] + h1; s1 = (v >= 1.f) ? 1.f : 0.f; v3[4*qq+1] = v - s1;
                v = v3[4*qq+2] + h2; s2 = (v >= 1.f) ? 1.f : 0.f; v3[4*qq+2] = v - s2;
                v = v3[4*qq+3] + h3; s3 = (v >= 1.f) ? 1.f : 0.f; v3[4*qq+3] = v - s3;
                s_spk[o][qq] = make_float4(s0, s1, s2, s3);
            }
        }
        __syncthreads();

        // ================= layer 4: 256->16 GEMM, write output ==============
        {
            unsigned long long acc = 0ull;
#pragma unroll 4
            for (int i = 0; i < HID; i++) {
                float w = __ldg(&g_w4t[i * 16 + o4]);
                float4 f = s_spk[i][q4];
                float slo = hiPair ? f.z : f.x;
                float shi = hiPair ? f.w : f.y;
                ffma2(acc, pk2(slo, shi), pk2(w, w));
            }
            float a0, a1v;
            up2(acc, a0, a1v);
            // output layout [T, B, 16]; this thread covers rows 2g, 2g+1
            size_t base = ((size_t)t * BATCH + (size_t)(rb + 2 * g)) * 16 + o4;
            out[base]      = a0;
            out[base + 16] = a1v;
        }
        __syncthreads();   // protect s_spk before next-t IF1 overwrite
    }
}

extern "C" void kernel_launch(void* const* d_in, const int* in_sizes, int n_in,
                              void* d_out, int out_size) {
    const float* x  = (const float*)d_in[0];
    const float* w1 = (const float*)d_in[1];
    const float* w2 = (const float*)d_in[2];
    const float* w3 = (const float*)d_in[3];
    const float* w4 = (const float*)d_in[4];
    float* out = (float*)d_out;

    prep_kernel<<<256, 256>>>(w2, w3, w4);
    snn_kernel<<<NBLK, 256>>>(x, w1, out);
}

// round 8
// speedup vs baseline: 1.2013x; 1.2013x over previous
#include <cuda_runtime.h>
#include <cstdint>

#define T_STEPS 16
#define BATCH   32768
#define M_CTA   128
#define NBLK    (BATCH / M_CTA)   // 256 CTAs
#define NTHR    512               // 16 warps

#define SW_OFF   0u               // weight quarter: 256 i x 64 o f32 = 64KB
#define BIN_OFF  65536u           // bit buffer A: [t][r][16 u16] = 64KB
#define BOUT_OFF 131072u          // bit buffer B: 64KB
#define SMEM_BYTES 196608u

// weights transposed + quartered: [L][q][i][o'] = w[(q*64+o')][i]
__device__ float g_w23t[2][4][256][64];
__device__ float g_w4t[256][16];

__global__ void prep_kernel(const float* __restrict__ w2, const float* __restrict__ w3,
                            const float* __restrict__ w4) {
    int idx = blockIdx.x * 256 + threadIdx.x;      // grid 512 -> 0..131071
    int L = idx >> 16;
    int o = (idx >> 8) & 255;
    int i = idx & 255;
    g_w23t[L][o >> 6][i][o & 63] = (L ? w3 : w2)[o * 256 + i];
    if (idx < 4096) {
        int ii = idx >> 4, oo = idx & 15;
        g_w4t[ii][oo] = w4[oo * 256 + ii];
    }
}

// ---- packed f32x2 helpers ----
__device__ __forceinline__ unsigned long long pku(uint32_t a, uint32_t b) {
    unsigned long long r;
    asm("mov.b64 %0, {%1,%2};" : "=l"(r) : "r"(a), "r"(b));
    return r;
}
__device__ __forceinline__ unsigned long long pkf(float a, float b) {
    unsigned long long r;
    asm("mov.b64 %0, {%1,%2};" : "=l"(r) : "f"(a), "f"(b));
    return r;
}
__device__ __forceinline__ void up2(unsigned long long v, float& a, float& b) {
    asm("mov.b64 {%0,%1}, %2;" : "=f"(a), "=f"(b) : "l"(v));
}
__device__ __forceinline__ void ffma2(unsigned long long& d,
                                      unsigned long long a, unsigned long long b) {
    asm("fma.rn.f32x2 %0, %1, %2, %0;" : "+l"(d) : "l"(a), "l"(b));
}
__device__ __forceinline__ unsigned long long add2(unsigned long long a,
                                                   unsigned long long b) {
    unsigned long long r;
    asm("add.rn.f32x2 %0, %1, %2;" : "=l"(r) : "l"(a), "l"(b));
    return r;
}

extern __shared__ __align__(16) unsigned char smem[];

__global__ __launch_bounds__(NTHR, 1)
void snn_kernel(const float* __restrict__ x, const float* __restrict__ w1,
                float* __restrict__ out) {
    const int tid  = threadIdx.x;
    const int wid  = tid >> 5;
    const int lane = tid & 31;
    const int cta  = blockIdx.x;
    const int rb   = cta * M_CTA;
    const int rg   = wid >> 2;          // 4 row groups x 32 rows
    const int oc   = wid & 3;           // 4 o-chunks x 16 o (within 64-o quarter)
    const int r    = rg * 32 + lane;

    // ================= layer 1: scalar fp32 IF (chain-exact) ================
    {
        float* sx  = (float*)(smem + SW_OFF);          // [128][16]
        float* sw1 = (float*)(smem + SW_OFF + 8192);   // [256][16]
        for (int idx = tid; idx < 128 * 16; idx += NTHR) sx[idx]  = x[rb * 16 + idx];
        for (int idx = tid; idx < 256 * 16; idx += NTHR) sw1[idx] = w1[idx];
        __syncthreads();
        const int rr = tid >> 2, h = tid & 3;          // row, o-64-group
        float xr[16];
#pragma unroll
        for (int k = 0; k < 16; k++) xr[k] = sx[rr * 16 + k];
        unsigned long long m[T_STEPS];
#pragma unroll
        for (int t = 0; t < T_STEPS; t++) m[t] = 0ull;
        for (int j = 0; j < 64; j++) {
            const int o = h * 64 + j;
            float a = 0.f;
#pragma unroll
            for (int k = 0; k < 16; k++) a = fmaf(xr[k], sw1[o * 16 + k], a);
            float v = 0.f;
#pragma unroll
            for (int t = 0; t < T_STEPS; t++) {
                v += a;
                if (v >= 1.f) { v -= 1.f; m[t] |= (1ull << j); }
            }
        }
#pragma unroll
        for (int t = 0; t < T_STEPS; t++)
            *(unsigned long long*)(smem + BIN_OFF + (t * 128 + rr) * 32 + h * 8) = m[t];
    }

    // ========== layers 2 & 3: chain-exact f32x2 sum-of-columns ==============
    for (int L = 0; L < 2; L++) {
        const unsigned char* pin  = smem + (L == 0 ? BIN_OFF : BOUT_OFF);
        unsigned char*       pout = smem + (L == 0 ? BOUT_OFF : BIN_OFF);
        for (int q = 0; q < 4; q++) {
            __syncthreads();
            {   // stage o-quarter weights (64KB)
                const uint4* src = (const uint4*)&g_w23t[L][q][0][0];
                uint4* dst = (uint4*)(smem + SW_OFF);
#pragma unroll
                for (int it = 0; it < 8; it++)
                    dst[tid + it * NTHR] = src[tid + it * NTHR];
            }
            __syncthreads();

            unsigned long long vv[8];                  // membrane: 16 o as 8 pairs
#pragma unroll
            for (int p = 0; p < 8; p++) vv[p] = 0ull;

            for (int t = 0; t < T_STEPS; t++) {
                unsigned long long acc[8];
#pragma unroll
                for (int p = 0; p < 8; p++) acc[p] = 0ull;

                const unsigned char* prow = pin + (t * 128 + r) * 32;
#pragma unroll 1
                for (int w = 0; w < 8; w++) {
                    const uint32_t Wb = *(const uint32_t*)(prow + w * 4);
                    const unsigned char* wbase =
                        smem + SW_OFF + (size_t)((w * 32) * 64 + oc * 16) * 4;
#pragma unroll
                    for (int b = 0; b < 32; b++) {
                        const uint32_t fb = ((Wb >> b) & 1u) * 0x3F800000u;
                        const unsigned long long mult = pku(fb, fb);
                        const ulonglong2* wp =
                            (const ulonglong2*)(wbase + (size_t)b * 256);
                        ulonglong2 p0 = wp[0], p1 = wp[1], p2 = wp[2], p3 = wp[3];
                        ffma2(acc[0], mult, p0.x); ffma2(acc[1], mult, p0.y);
                        ffma2(acc[2], mult, p1.x); ffma2(acc[3], mult, p1.y);
                        ffma2(acc[4], mult, p2.x); ffma2(acc[5], mult, p2.y);
                        ffma2(acc[6], mult, p3.x); ffma2(acc[7], mult, p3.y);
                    }
                }

                // IF: v += a (RN), spike, soft reset — matches reference order
                uint32_t m16 = 0;
#pragma unroll
                for (int p = 0; p < 8; p++) {
                    vv[p] = add2(vv[p], acc[p]);
                    float f0, f1; up2(vv[p], f0, f1);
                    if (f0 >= 1.f) { f0 -= 1.f; m16 |= 1u << (2 * p); }
                    if (f1 >= 1.f) { f1 -= 1.f; m16 |= 2u << (2 * p); }
                    vv[p] = pkf(f0, f1);
                }
                *(uint16_t*)(pout + (t * 128 + r) * 32 + (q * 4 + oc) * 2) =
                    (uint16_t)m16;
            }
        }
    }

    // ================= layer 4: 256->16 (no thresholds after) ===============
    __syncthreads();
    {
        const uint4* src = (const uint4*)&g_w4t[0][0];
        uint4* dst = (uint4*)(smem + SW_OFF);
        for (int idx = tid; idx < 1024; idx += NTHR) dst[idx] = src[idx];
    }
    __syncthreads();
    {
        const unsigned char* pin = smem + BIN_OFF;     // layer-3 spikes
        for (int pass = 0; pass < 4; pass++) {
            const int item = pass * NTHR + tid;        // 2048 items = (t, r)
            const int t  = item >> 7;
            const int rr = item & 127;
            const unsigned char* prow = pin + (t * 128 + rr) * 32;
            unsigned long long acc[8];
#pragma unroll
            for (int p = 0; p < 8; p++) acc[p] = 0ull;
#pragma unroll 1
            for (int w = 0; w < 8; w++) {
                const uint32_t Wb = *(const uint32_t*)(prow + w * 4);
                const unsigned char* wbase = smem + SW_OFF + (size_t)(w * 32) * 64;
#pragma unroll
                for (int b = 0; b < 32; b++) {
                    const uint32_t fb = ((Wb >> b) & 1u) * 0x3F800000u;
                    const unsigned long long mult = pku(fb, fb);
                    const ulonglong2* wp = (const ulonglong2*)(wbase + (size_t)b * 64);
                    ulonglong2 p0 = wp[0], p1 = wp[1], p2 = wp[2], p3 = wp[3];
                    ffma2(acc[0], mult, p0.x); ffma2(acc[1], mult, p0.y);
                    ffma2(acc[2], mult, p1.x); ffma2(acc[3], mult, p1.y);
                    ffma2(acc[4], mult, p2.x); ffma2(acc[5], mult, p2.y);
                    ffma2(acc[6], mult, p3.x); ffma2(acc[7], mult, p3.y);
                }
            }
            float* po = out + ((size_t)t * BATCH + rb + rr) * 16;
#pragma unroll
            for (int p = 0; p < 8; p++)
                *(unsigned long long*)(po + 2 * p) = acc[p];
        }
    }
}

extern "C" void kernel_launch(void* const* d_in, const int* in_sizes, int n_in,
                              void* d_out, int out_size) {
    const float* x  = (const float*)d_in[0];
    const float* w1 = (const float*)d_in[1];
    const float* w2 = (const float*)d_in[2];
    const float* w3 = (const float*)d_in[3];
    const float* w4 = (const float*)d_in[4];
    float* out = (float*)d_out;

    cudaFuncSetAttribute(snn_kernel, cudaFuncAttributeMaxDynamicSharedMemorySize,
                         SMEM_BYTES);
    prep_kernel<<<512, 256>>>(w2, w3, w4);
    snn_kernel<<<NBLK, NTHR, SMEM_BYTES>>>(x, w1, out);
}